// round 3
// baseline (speedup 1.0000x reference)
#include <cuda_runtime.h>
#include <cstdint>

#define NPROP 1000
#define CCH 256
#define FEATLEN 12544   // 256*7*7
#define DH 1024

// ---- static scratch (no allocation allowed) ----
__device__ float g_featT[22848000];           // transposed features [HW, C], 91.4 MB
__device__ float g_x0[NPROP * FEATLEN];       // pooled ROI rows, 50.2 MB
__device__ float g_x1[NPROP * DH];
__device__ float g_x2[NPROP * DH];

__constant__ int c_W[4]    = {336, 168, 84, 42};
__constant__ int c_H[4]    = {200, 100, 50, 25};
__constant__ int c_off[4]  = {0, 17203200, 21504000, 22579200};

// ======================= transpose [C,HW] -> [HW,C] =======================
__global__ void transpose_kernel(const float* __restrict__ in,
                                 float* __restrict__ out, int HW) {
    __shared__ float tile[32][33];
    int hw0 = blockIdx.x * 32;
    int c0  = blockIdx.y * 32;
    int x = hw0 + threadIdx.x;
#pragma unroll
    for (int i = 0; i < 32; i += 8) {
        int c = c0 + threadIdx.y + i;   // c < 256 always (grid.y = 8)
        if (x < HW) tile[threadIdx.y + i][threadIdx.x] = in[(size_t)c * HW + x];
    }
    __syncthreads();
    int c = c0 + threadIdx.x;
#pragma unroll
    for (int i = 0; i < 32; i += 8) {
        int hw = hw0 + threadIdx.y + i;
        if (hw < HW) out[(size_t)hw * CCH + c] = tile[threadIdx.x][threadIdx.y + i];
    }
}

// ======================= ROI align + 2x2 avg pool =========================
// one block per proposal, 256 threads = one per channel
__global__ void roi_kernel(const float* __restrict__ proposals) {
    extern __shared__ float stile[];  // 12544 floats
    __shared__ int   sx0[14], sx1[14], sy0[14], sy1[14];
    __shared__ float sfx[14], sfy[14];
    __shared__ int   svx[14], svy[14];
    __shared__ float sp[4];
    __shared__ int   s_li;

    int n = blockIdx.x;
    int tid = threadIdx.x;

    if (tid < 4) sp[tid] = proposals[n * 4 + tid];
    __syncthreads();
    float px1 = sp[0], py1 = sp[1], px2 = sp[2], py2 = sp[3];

    if (tid == 0) {
        float h = py2 - py1, w = px2 - px1;
        float sqrtarea = sqrtf(h * w);
        float lf = 4.0f + logf(sqrtarea / 224.0f + 1e-6f) / logf(2.0f);
        int lvl = (int)lf;                 // truncation toward zero == astype(int32)
        lvl = min(max(lvl, 2), 5);
        s_li = lvl - 2;
    }
    __syncthreads();
    int li = s_li;
    int W = c_W[li], H = c_H[li];
    int Wp = W + 2, Hp = H + 2;
    float inv_stride = 1.0f / (float)(4 << li);
    float bx1 = px1 * inv_stride + 1.0f, by1 = py1 * inv_stride + 1.0f;
    float bx2 = px2 * inv_stride + 1.0f, by2 = py2 * inv_stride + 1.0f;

    if (tid < 14) {
        float g = ((float)tid + 0.5f) / 14.0f;
        float xc = bx1 + g * (bx2 - bx1) - 0.5f;
        svx[tid] = (xc >= -1.0f) && (xc <= (float)Wp);
        float cx = fminf(fmaxf(xc, 0.0f), (float)(Wp - 1));
        int lo = (int)floorf(cx);
        int hi = min(lo + 1, Wp - 1);
        sfx[tid] = cx - (float)lo;
        sx0[tid] = min(max(lo - 1, 0), W - 1);   // padded->orig (edge pad == clamp)
        sx1[tid] = min(max(hi - 1, 0), W - 1);
        float yc = by1 + g * (by2 - by1) - 0.5f;
        svy[tid] = (yc >= -1.0f) && (yc <= (float)Hp);
        float cy = fminf(fmaxf(yc, 0.0f), (float)(Hp - 1));
        int lo2 = (int)floorf(cy);
        int hi2 = min(lo2 + 1, Hp - 1);
        sfy[tid] = cy - (float)lo2;
        sy0[tid] = min(max(lo2 - 1, 0), H - 1);
        sy1[tid] = min(max(hi2 - 1, 0), H - 1);
    }
    __syncthreads();

    int c = tid;  // channel
    const float* fbase = g_featT + c_off[li];
#pragma unroll 1
    for (int oy = 0; oy < 7; oy++) {
#pragma unroll 1
        for (int ox = 0; ox < 7; ox++) {
            float acc = 0.0f;
#pragma unroll
            for (int s = 0; s < 4; s++) {
                int gy = 2 * oy + (s >> 1);
                int gx = 2 * ox + (s & 1);
                if (svx[gx] && svy[gy]) {
                    float fx = sfx[gx], fy = sfy[gy];
                    int x0i = sx0[gx], x1i = sx1[gx];
                    int y0i = sy0[gy], y1i = sy1[gy];
                    const float* r0 = fbase + (size_t)(y0i * W) * CCH;
                    const float* r1 = fbase + (size_t)(y1i * W) * CCH;
                    float v00 = r0[x0i * CCH + c];
                    float v01 = r0[x1i * CCH + c];
                    float v10 = r1[x0i * CCH + c];
                    float v11 = r1[x1i * CCH + c];
                    float v = v00 * ((1.0f - fy) * (1.0f - fx))
                            + v01 * ((1.0f - fy) * fx)
                            + v10 * (fy * (1.0f - fx))
                            + v11 * (fy * fx);
                    acc += v;
                }
            }
            stile[c * 49 + oy * 7 + ox] = acc * 0.25f;
        }
    }
    __syncthreads();
    float* xrow = g_x0 + (size_t)n * FEATLEN;
    for (int i = tid; i < FEATLEN; i += 256) xrow[i] = stile[i];
}

// ======================= SGEMM  C = relu(A*B + bias) ======================
// A [M,K] row-major, B [K,N] row-major. BM=128 BN=64 BK=8, 256 thr, 8x4/thr.
// Double-buffered smem + register prefetch: ONE __syncthreads per K-tile.
template <bool RELU>
__global__ __launch_bounds__(256) void sgemm_bias(
        const float* __restrict__ A, const float* __restrict__ B,
        const float* __restrict__ bias, float* __restrict__ Cm,
        int M, int N, int K) {
    const int BM = 128, BN = 64, BK = 8;
    __shared__ float As[2][BK][BM];
    __shared__ float Bs[2][BK][BN];
    int tid = threadIdx.x;
    int brow = blockIdx.y * BM;
    int bcol = blockIdx.x * BN;
    int trow = (tid >> 4) * 8;
    int tcol = (tid & 15) * 4;
    int a_r = tid >> 1;
    int a_k = (tid & 1) * 4;
    int b_k = tid >> 5;
    int b_n = (tid & 31) * 2;

    float acc[8][4];
#pragma unroll
    for (int i = 0; i < 8; i++)
#pragma unroll
        for (int j = 0; j < 4; j++) acc[i][j] = 0.0f;

    bool a_valid = (brow + a_r) < M;
    const float* Ap = A + (size_t)(brow + a_r) * K + a_k;
    const float* Bp = B + (size_t)b_k * N + bcol + b_n;

    // prologue: load tile 0 into smem buffer 0
    {
        float4 av = make_float4(0.f, 0.f, 0.f, 0.f);
        if (a_valid) av = *(const float4*)(Ap);
        float2 bv = *(const float2*)(Bp);
        As[0][a_k + 0][a_r] = av.x;
        As[0][a_k + 1][a_r] = av.y;
        As[0][a_k + 2][a_r] = av.z;
        As[0][a_k + 3][a_r] = av.w;
        Bs[0][b_k][b_n]     = bv.x;
        Bs[0][b_k][b_n + 1] = bv.y;
    }
    __syncthreads();

    int buf = 0;
    for (int k0 = 0; k0 < K; k0 += BK) {
        // prefetch next tile into registers (overlaps with FMAs)
        int kn = k0 + BK;
        float4 av = make_float4(0.f, 0.f, 0.f, 0.f);
        float2 bv = make_float2(0.f, 0.f);
        if (kn < K) {
            if (a_valid) av = *(const float4*)(Ap + kn);
            bv = *(const float2*)(Bp + (size_t)kn * N);
        }

#pragma unroll
        for (int kk = 0; kk < BK; kk++) {
            float4 a0 = *(const float4*)&As[buf][kk][trow];
            float4 a1 = *(const float4*)&As[buf][kk][trow + 4];
            float4 b0 = *(const float4*)&Bs[buf][kk][tcol];
            float ar[8] = {a0.x, a0.y, a0.z, a0.w, a1.x, a1.y, a1.z, a1.w};
            float br[4] = {b0.x, b0.y, b0.z, b0.w};
#pragma unroll
            for (int i = 0; i < 8; i++)
#pragma unroll
                for (int j = 0; j < 4; j++)
                    acc[i][j] = fmaf(ar[i], br[j], acc[i][j]);
        }

        if (kn < K) {
            int nb = buf ^ 1;
            As[nb][a_k + 0][a_r] = av.x;
            As[nb][a_k + 1][a_r] = av.y;
            As[nb][a_k + 2][a_r] = av.z;
            As[nb][a_k + 3][a_r] = av.w;
            Bs[nb][b_k][b_n]     = bv.x;
            Bs[nb][b_k][b_n + 1] = bv.y;
            __syncthreads();
            buf = nb;
        }
    }

#pragma unroll
    for (int i = 0; i < 8; i++) {
        int row = brow + trow + i;
        if (row >= M) continue;
        float4 v;
        v.x = acc[i][0] + bias[bcol + tcol + 0];
        v.y = acc[i][1] + bias[bcol + tcol + 1];
        v.z = acc[i][2] + bias[bcol + tcol + 2];
        v.w = acc[i][3] + bias[bcol + tcol + 3];
        if (RELU) {
            v.x = fmaxf(v.x, 0.f); v.y = fmaxf(v.y, 0.f);
            v.z = fmaxf(v.z, 0.f); v.w = fmaxf(v.w, 0.f);
        }
        *(float4*)(Cm + (size_t)row * N + bcol + tcol) = v;
    }
}

// ======================= heads + softmax + decode =========================
__global__ void heads_kernel(const float* __restrict__ cls_w, const float* __restrict__ cls_b,
                             const float* __restrict__ box_w, const float* __restrict__ box_b,
                             const float* __restrict__ cos_w, const float* __restrict__ cos_b,
                             const float* __restrict__ sin_w, const float* __restrict__ sin_b,
                             const float* __restrict__ proposals,
                             const float* __restrict__ img,
                             float* __restrict__ out) {
    int n = blockIdx.x, tid = threadIdx.x;
    __shared__ float xs[DH];
    __shared__ float hout[88];
    __shared__ float ev[81];
    __shared__ float red[2];

    for (int k = tid; k < DH; k += 128) xs[k] = g_x2[(size_t)n * DH + k];
    __syncthreads();

    if (tid < 81) {
        float a = 0.f;
        for (int k = 0; k < DH; k++) a = fmaf(xs[k], cls_w[k * 81 + tid], a);
        hout[tid] = a + cls_b[tid];
    } else if (tid < 85) {
        int j = tid - 81;
        float a = 0.f;
        for (int k = 0; k < DH; k++) a = fmaf(xs[k], box_w[k * 4 + j], a);
        hout[tid] = a + box_b[j];
    } else if (tid == 85) {
        float a = 0.f;
        for (int k = 0; k < DH; k++) a = fmaf(xs[k], cos_w[k], a);
        hout[85] = a + cos_b[0];
    } else if (tid == 86) {
        float a = 0.f;
        for (int k = 0; k < DH; k++) a = fmaf(xs[k], sin_w[k], a);
        hout[86] = a + sin_b[0];
    }
    __syncthreads();

    if (tid == 0) {
        float mx = hout[0];
        for (int j = 1; j < 81; j++) mx = fmaxf(mx, hout[j]);
        red[0] = mx;
    }
    __syncthreads();
    if (tid < 81) ev[tid] = expf(hout[tid] - red[0]);
    __syncthreads();
    if (tid == 0) {
        float s = 0.f;
        for (int j = 0; j < 81; j++) s += ev[j];
        red[1] = s;
    }
    __syncthreads();

    // output layout: scores | logits | box_logits | cos | sin | boxes
    if (tid < 81) {
        out[n * 81 + tid]          = ev[tid] / red[1];
        out[81000 + n * 81 + tid]  = hout[tid];
    } else if (tid < 85) {
        out[162000 + n * 4 + (tid - 81)] = hout[tid];
    } else if (tid == 85) {
        out[166000 + n] = hout[85];
    } else if (tid == 86) {
        out[167000 + n] = hout[86];
    }

    if (tid == 0) {
        float x1p = proposals[n * 4 + 0], y1p = proposals[n * 4 + 1];
        float x2p = proposals[n * 4 + 2], y2p = proposals[n * 4 + 3];
        float tx = hout[81] / 10.0f, ty = hout[82] / 10.0f;
        float tw = hout[83] / 5.0f,  th = hout[84] / 5.0f;
        float wa = x2p - x1p, ha = y2p - y1p;
        float xa = (x1p + x2p) * 0.5f, ya = (y1p + y2p) * 0.5f;
        const float clipv = 4.430816798843313f;  // log(1344/16)
        float wb = expf(fminf(tw, clipv)) * wa;
        float hb = expf(fminf(th, clipv)) * ha;
        float xb = tx * wa + xa, yb = ty * ha + ya;
        float s0 = img[0], s1 = img[1];   // reference clips x by shape[0](=800), y by shape[1](=1344)
        out[168000 + n * 4 + 0] = fminf(fmaxf(xb - wb * 0.5f, 0.f), s0);
        out[168000 + n * 4 + 1] = fminf(fmaxf(yb - hb * 0.5f, 0.f), s1);
        out[168000 + n * 4 + 2] = fminf(fmaxf(xb + wb * 0.5f, 0.f), s0);
        out[168000 + n * 4 + 3] = fminf(fmaxf(yb + hb * 0.5f, 0.f), s1);
    }
}

// ======================= launch =========================
extern "C" void kernel_launch(void* const* d_in, const int* in_sizes, int n_in,
                              void* d_out, int out_size) {
    const float* img       = (const float*)d_in[0];
    const float* proposals = (const float*)d_in[1];
    const float* fc6_w = (const float*)d_in[2];
    const float* fc6_b = (const float*)d_in[3];
    const float* fc7_w = (const float*)d_in[4];
    const float* fc7_b = (const float*)d_in[5];
    const float* cls_w = (const float*)d_in[6];
    const float* cls_b = (const float*)d_in[7];
    const float* box_w = (const float*)d_in[8];
    const float* box_b = (const float*)d_in[9];
    const float* cos_w = (const float*)d_in[10];
    const float* cos_b = (const float*)d_in[11];
    const float* sin_w = (const float*)d_in[12];
    const float* sin_b = (const float*)d_in[13];
    const float* feats[4] = {(const float*)d_in[14], (const float*)d_in[15],
                             (const float*)d_in[16], (const float*)d_in[17]};
    float* out = (float*)d_out;

    float *featT, *x0, *x1, *x2;
    cudaGetSymbolAddress((void**)&featT, g_featT);
    cudaGetSymbolAddress((void**)&x0, g_x0);
    cudaGetSymbolAddress((void**)&x1, g_x1);
    cudaGetSymbolAddress((void**)&x2, g_x2);

    const int HWs[4]     = {67200, 16800, 4200, 1050};
    const size_t offs[4] = {0, 17203200, 21504000, 22579200};
    for (int l = 0; l < 4; l++) {
        dim3 grid((HWs[l] + 31) / 32, 8), block(32, 8);
        transpose_kernel<<<grid, block>>>(feats[l], featT + offs[l], HWs[l]);
    }

    cudaFuncSetAttribute(roi_kernel, cudaFuncAttributeMaxDynamicSharedMemorySize, 50176);
    roi_kernel<<<NPROP, 256, 50176>>>(proposals);

    dim3 g6(1024 / 64, (NPROP + 127) / 128);  // (16, 8)
    sgemm_bias<true><<<g6, 256>>>(x0, fc6_w, fc6_b, x1, NPROP, 1024, 12544);
    sgemm_bias<true><<<g6, 256>>>(x1, fc7_w, fc7_b, x2, NPROP, 1024, 1024);

    heads_kernel<<<NPROP, 128>>>(cls_w, cls_b, box_w, box_b,
                                 cos_w, cos_b, sin_w, sin_b,
                                 proposals, img, out);
}

// round 5
// speedup vs baseline: 2.4532x; 2.4532x over previous
#include <cuda_runtime.h>
#include <cstdint>

#define NPROP 1000
#define CCH 256
#define FEATLEN 12544   // 256*7*7
#define DH 1024

// ---- static scratch (no allocation allowed) ----
__device__ float g_featT[22848000];           // transposed features [HW, C], 91.4 MB
__device__ float g_x0[NPROP * FEATLEN];       // pooled ROI rows, 50.2 MB
__device__ float g_x1[NPROP * DH];
__device__ float g_x2[NPROP * DH];

__constant__ int c_W[4]    = {336, 168, 84, 42};
__constant__ int c_H[4]    = {200, 100, 50, 25};
__constant__ int c_off[4]  = {0, 17203200, 21504000, 22579200};

// ======================= transpose [C,HW] -> [HW,C] =======================
__global__ void transpose_kernel(const float* __restrict__ in,
                                 float* __restrict__ out, int HW) {
    __shared__ float tile[32][33];
    int hw0 = blockIdx.x * 32;
    int c0  = blockIdx.y * 32;
    int x = hw0 + threadIdx.x;
#pragma unroll
    for (int i = 0; i < 32; i += 8) {
        int c = c0 + threadIdx.y + i;   // c < 256 always (grid.y = 8)
        if (x < HW) tile[threadIdx.y + i][threadIdx.x] = in[(size_t)c * HW + x];
    }
    __syncthreads();
    int c = c0 + threadIdx.x;
#pragma unroll
    for (int i = 0; i < 32; i += 8) {
        int hw = hw0 + threadIdx.y + i;
        if (hw < HW) out[(size_t)hw * CCH + c] = tile[threadIdx.x][threadIdx.y + i];
    }
}

// ======================= ROI align + 2x2 avg pool =========================
// one block per proposal, 256 threads = one per channel
__global__ void roi_kernel(const float* __restrict__ proposals) {
    extern __shared__ float stile[];  // 12544 floats
    __shared__ int   sx0[14], sx1[14], sy0[14], sy1[14];
    __shared__ float sfx[14], sfy[14];
    __shared__ int   svx[14], svy[14];
    __shared__ float sp[4];
    __shared__ int   s_li;

    int n = blockIdx.x;
    int tid = threadIdx.x;

    if (tid < 4) sp[tid] = proposals[n * 4 + tid];
    __syncthreads();
    float px1 = sp[0], py1 = sp[1], px2 = sp[2], py2 = sp[3];

    if (tid == 0) {
        float h = py2 - py1, w = px2 - px1;
        float sqrtarea = sqrtf(h * w);
        float lf = 4.0f + logf(sqrtarea / 224.0f + 1e-6f) / logf(2.0f);
        int lvl = (int)lf;                 // truncation toward zero == astype(int32)
        lvl = min(max(lvl, 2), 5);
        s_li = lvl - 2;
    }
    __syncthreads();
    int li = s_li;
    int W = c_W[li], H = c_H[li];
    int Wp = W + 2, Hp = H + 2;
    float inv_stride = 1.0f / (float)(4 << li);
    float bx1 = px1 * inv_stride + 1.0f, by1 = py1 * inv_stride + 1.0f;
    float bx2 = px2 * inv_stride + 1.0f, by2 = py2 * inv_stride + 1.0f;

    if (tid < 14) {
        float g = ((float)tid + 0.5f) / 14.0f;
        float xc = bx1 + g * (bx2 - bx1) - 0.5f;
        svx[tid] = (xc >= -1.0f) && (xc <= (float)Wp);
        float cx = fminf(fmaxf(xc, 0.0f), (float)(Wp - 1));
        int lo = (int)floorf(cx);
        int hi = min(lo + 1, Wp - 1);
        sfx[tid] = cx - (float)lo;
        sx0[tid] = min(max(lo - 1, 0), W - 1);   // padded->orig (edge pad == clamp)
        sx1[tid] = min(max(hi - 1, 0), W - 1);
        float yc = by1 + g * (by2 - by1) - 0.5f;
        svy[tid] = (yc >= -1.0f) && (yc <= (float)Hp);
        float cy = fminf(fmaxf(yc, 0.0f), (float)(Hp - 1));
        int lo2 = (int)floorf(cy);
        int hi2 = min(lo2 + 1, Hp - 1);
        sfy[tid] = cy - (float)lo2;
        sy0[tid] = min(max(lo2 - 1, 0), H - 1);
        sy1[tid] = min(max(hi2 - 1, 0), H - 1);
    }
    __syncthreads();

    int c = tid;  // channel
    const float* fbase = g_featT + c_off[li];
#pragma unroll 1
    for (int oy = 0; oy < 7; oy++) {
#pragma unroll 1
        for (int ox = 0; ox < 7; ox++) {
            float acc = 0.0f;
#pragma unroll
            for (int s = 0; s < 4; s++) {
                int gy = 2 * oy + (s >> 1);
                int gx = 2 * ox + (s & 1);
                if (svx[gx] && svy[gy]) {
                    float fx = sfx[gx], fy = sfy[gy];
                    int x0i = sx0[gx], x1i = sx1[gx];
                    int y0i = sy0[gy], y1i = sy1[gy];
                    const float* r0 = fbase + (size_t)(y0i * W) * CCH;
                    const float* r1 = fbase + (size_t)(y1i * W) * CCH;
                    float v00 = r0[x0i * CCH + c];
                    float v01 = r0[x1i * CCH + c];
                    float v10 = r1[x0i * CCH + c];
                    float v11 = r1[x1i * CCH + c];
                    float v = v00 * ((1.0f - fy) * (1.0f - fx))
                            + v01 * ((1.0f - fy) * fx)
                            + v10 * (fy * (1.0f - fx))
                            + v11 * (fy * fx);
                    acc += v;
                }
            }
            stile[c * 49 + oy * 7 + ox] = acc * 0.25f;
        }
    }
    __syncthreads();
    float* xrow = g_x0 + (size_t)n * FEATLEN;
    for (int i = tid; i < FEATLEN; i += 256) xrow[i] = stile[i];
}

// ======================= tf32 tensor-core GEMM ============================
// C = relu(A*B + bias).  A [M,K] row-major fp32, B [K,N] row-major fp32.
// BM=128 BN=64 BK=16, 256 threads = 8 warps (4 m-warps x 2 n-warps),
// warp tile 32x32 via mma.sync.m16n8k8.tf32. cp.async double buffering.

__device__ __forceinline__ uint32_t f2tf32(float f) {
    uint32_t u;
    asm("cvt.rna.tf32.f32 %0, %1;" : "=r"(u) : "f"(f));
    return u;
}
__device__ __forceinline__ uint32_t smem_u32(const void* p) {
    return (uint32_t)__cvta_generic_to_shared(p);
}
__device__ __forceinline__ void cp_async16(uint32_t dst, const void* src, int srcsize) {
    asm volatile("cp.async.ca.shared.global [%0], [%1], 16, %2;\n"
                 :: "r"(dst), "l"(src), "r"(srcsize));
}

template <bool RELU>
__global__ __launch_bounds__(256) void mma_gemm(
        const float* __restrict__ A, const float* __restrict__ B,
        const float* __restrict__ bias, float* __restrict__ Cm,
        int M, int N, int K) {
    const int BM = 128, BN = 64, BK = 16;
    __shared__ float As[2][BM][BK + 4];   // [m][k], row stride 20 fl = 80B (16B-mult)
    __shared__ float Bs[2][BK][BN + 4];   // [k][n], row stride 68 fl = 272B (16B-mult)

    int tid  = threadIdx.x;
    int wid  = tid >> 5;
    int lane = tid & 31;
    int brow = blockIdx.y * BM;
    int bcol = blockIdx.x * BN;
    int warp_m = (wid & 3) * 32;
    int warp_n = (wid >> 2) * 32;

    // ---- global->smem load mapping ----
    int a_row0 = tid >> 2;           // rows 0..63 (second slot: +64)
    int a_kq   = (tid & 3) * 4;      // k offset in floats
    int b_k  = tid >> 4;
    int b_nq = (tid & 15) * 4;

    int T = K / BK;   // K is a multiple of 16 for both GEMMs

    auto load_tile = [&](int t, int buf) {
        int k0 = t * BK;
        {
            int r = a_row0;
            int grow = brow + r;
            const float* src = A + (size_t)min(grow, M - 1) * K + k0 + a_kq;
            cp_async16(smem_u32(&As[buf][r][a_kq]), src, grow < M ? 16 : 0);
            r += 64; grow = brow + r;
            src = A + (size_t)min(grow, M - 1) * K + k0 + a_kq;
            cp_async16(smem_u32(&As[buf][r][a_kq]), src, grow < M ? 16 : 0);
        }
        {
            const float* src = B + (size_t)(k0 + b_k) * N + bcol + b_nq;
            cp_async16(smem_u32(&Bs[buf][b_k][b_nq]), src, 16);
        }
        asm volatile("cp.async.commit_group;\n" ::);
    };

    float acc[2][4][4];
#pragma unroll
    for (int i = 0; i < 2; i++)
#pragma unroll
        for (int j = 0; j < 4; j++)
#pragma unroll
            for (int r = 0; r < 4; r++) acc[i][j][r] = 0.0f;

    // prologue: 2 tiles in flight
    load_tile(0, 0);
    if (T > 1) load_tile(1, 1);

    for (int t = 0; t < T; t++) {
        if (t + 1 < T) asm volatile("cp.async.wait_group 1;\n" ::);
        else           asm volatile("cp.async.wait_group 0;\n" ::);
        __syncthreads();
        int buf = t & 1;

#pragma unroll
        for (int ks = 0; ks < BK; ks += 8) {
            uint32_t a[2][4], b[4][2];
            int ar = (lane >> 2);
            int ac = ks + (lane & 3);
#pragma unroll
            for (int i = 0; i < 2; i++) {
                int r0 = warp_m + i * 16 + ar;
                a[i][0] = f2tf32(As[buf][r0][ac]);
                a[i][1] = f2tf32(As[buf][r0 + 8][ac]);
                a[i][2] = f2tf32(As[buf][r0][ac + 4]);
                a[i][3] = f2tf32(As[buf][r0 + 8][ac + 4]);
            }
            int bk0 = ks + (lane & 3);
#pragma unroll
            for (int j = 0; j < 4; j++) {
                int n0 = warp_n + j * 8 + (lane >> 2);
                b[j][0] = f2tf32(Bs[buf][bk0][n0]);
                b[j][1] = f2tf32(Bs[buf][bk0 + 4][n0]);
            }
#pragma unroll
            for (int i = 0; i < 2; i++)
#pragma unroll
                for (int j = 0; j < 4; j++) {
                    asm volatile(
                        "mma.sync.aligned.m16n8k8.row.col.f32.tf32.tf32.f32 "
                        "{%0,%1,%2,%3}, {%4,%5,%6,%7}, {%8,%9}, {%0,%1,%2,%3};\n"
                        : "+f"(acc[i][j][0]), "+f"(acc[i][j][1]),
                          "+f"(acc[i][j][2]), "+f"(acc[i][j][3])
                        : "r"(a[i][0]), "r"(a[i][1]), "r"(a[i][2]), "r"(a[i][3]),
                          "r"(b[j][0]), "r"(b[j][1]));
                }
        }
        __syncthreads();
        if (t + 2 < T) load_tile(t + 2, buf);
    }

    // ---- epilogue: bias + relu + store ----
#pragma unroll
    for (int i = 0; i < 2; i++) {
#pragma unroll
        for (int j = 0; j < 4; j++) {
            int col = bcol + warp_n + j * 8 + 2 * (lane & 3);
            float b0 = bias[col], b1 = bias[col + 1];
            int row0 = brow + warp_m + i * 16 + (lane >> 2);
            float v0 = acc[i][j][0] + b0, v1 = acc[i][j][1] + b1;
            float v2 = acc[i][j][2] + b0, v3 = acc[i][j][3] + b1;
            if (RELU) {
                v0 = fmaxf(v0, 0.f); v1 = fmaxf(v1, 0.f);
                v2 = fmaxf(v2, 0.f); v3 = fmaxf(v3, 0.f);
            }
            if (row0 < M) *(float2*)(Cm + (size_t)row0 * N + col) = make_float2(v0, v1);
            if (row0 + 8 < M) *(float2*)(Cm + (size_t)(row0 + 8) * N + col) = make_float2(v2, v3);
        }
    }
}

// ======================= heads + softmax + decode =========================
__global__ void heads_kernel(const float* __restrict__ cls_w, const float* __restrict__ cls_b,
                             const float* __restrict__ box_w, const float* __restrict__ box_b,
                             const float* __restrict__ cos_w, const float* __restrict__ cos_b,
                             const float* __restrict__ sin_w, const float* __restrict__ sin_b,
                             const float* __restrict__ proposals,
                             const float* __restrict__ img,
                             float* __restrict__ out) {
    int n = blockIdx.x, tid = threadIdx.x;
    __shared__ float xs[DH];
    __shared__ float hout[88];
    __shared__ float ev[81];
    __shared__ float red[2];

    for (int k = tid; k < DH; k += 128) xs[k] = g_x2[(size_t)n * DH + k];
    __syncthreads();

    if (tid < 81) {
        float a = 0.f;
        for (int k = 0; k < DH; k++) a = fmaf(xs[k], cls_w[k * 81 + tid], a);
        hout[tid] = a + cls_b[tid];
    } else if (tid < 85) {
        int j = tid - 81;
        float a = 0.f;
        for (int k = 0; k < DH; k++) a = fmaf(xs[k], box_w[k * 4 + j], a);
        hout[tid] = a + box_b[j];
    } else if (tid == 85) {
        float a = 0.f;
        for (int k = 0; k < DH; k++) a = fmaf(xs[k], cos_w[k], a);
        hout[85] = a + cos_b[0];
    } else if (tid == 86) {
        float a = 0.f;
        for (int k = 0; k < DH; k++) a = fmaf(xs[k], sin_w[k], a);
        hout[86] = a + sin_b[0];
    }
    __syncthreads();

    if (tid == 0) {
        float mx = hout[0];
        for (int j = 1; j < 81; j++) mx = fmaxf(mx, hout[j]);
        red[0] = mx;
    }
    __syncthreads();
    if (tid < 81) ev[tid] = expf(hout[tid] - red[0]);
    __syncthreads();
    if (tid == 0) {
        float s = 0.f;
        for (int j = 0; j < 81; j++) s += ev[j];
        red[1] = s;
    }
    __syncthreads();

    // output layout: scores | logits | box_logits | cos | sin | boxes
    if (tid < 81) {
        out[n * 81 + tid]          = ev[tid] / red[1];
        out[81000 + n * 81 + tid]  = hout[tid];
    } else if (tid < 85) {
        out[162000 + n * 4 + (tid - 81)] = hout[tid];
    } else if (tid == 85) {
        out[166000 + n] = hout[85];
    } else if (tid == 86) {
        out[167000 + n] = hout[86];
    }

    if (tid == 0) {
        float x1p = proposals[n * 4 + 0], y1p = proposals[n * 4 + 1];
        float x2p = proposals[n * 4 + 2], y2p = proposals[n * 4 + 3];
        float tx = hout[81] / 10.0f, ty = hout[82] / 10.0f;
        float tw = hout[83] / 5.0f,  th = hout[84] / 5.0f;
        float wa = x2p - x1p, ha = y2p - y1p;
        float xa = (x1p + x2p) * 0.5f, ya = (y1p + y2p) * 0.5f;
        const float clipv = 4.430816798843313f;  // log(1344/16)
        float wb = expf(fminf(tw, clipv)) * wa;
        float hb = expf(fminf(th, clipv)) * ha;
        float xb = tx * wa + xa, yb = ty * ha + ya;
        float s0 = img[0], s1 = img[1];   // reference clips x by shape[0](=800), y by shape[1](=1344)
        out[168000 + n * 4 + 0] = fminf(fmaxf(xb - wb * 0.5f, 0.f), s0);
        out[168000 + n * 4 + 1] = fminf(fmaxf(yb - hb * 0.5f, 0.f), s1);
        out[168000 + n * 4 + 2] = fminf(fmaxf(xb + wb * 0.5f, 0.f), s0);
        out[168000 + n * 4 + 3] = fminf(fmaxf(yb + hb * 0.5f, 0.f), s1);
    }
}

// ======================= launch =========================
extern "C" void kernel_launch(void* const* d_in, const int* in_sizes, int n_in,
                              void* d_out, int out_size) {
    const float* img       = (const float*)d_in[0];
    const float* proposals = (const float*)d_in[1];
    const float* fc6_w = (const float*)d_in[2];
    const float* fc6_b = (const float*)d_in[3];
    const float* fc7_w = (const float*)d_in[4];
    const float* fc7_b = (const float*)d_in[5];
    const float* cls_w = (const float*)d_in[6];
    const float* cls_b = (const float*)d_in[7];
    const float* box_w = (const float*)d_in[8];
    const float* box_b = (const float*)d_in[9];
    const float* cos_w = (const float*)d_in[10];
    const float* cos_b = (const float*)d_in[11];
    const float* sin_w = (const float*)d_in[12];
    const float* sin_b = (const float*)d_in[13];
    const float* feats[4] = {(const float*)d_in[14], (const float*)d_in[15],
                             (const float*)d_in[16], (const float*)d_in[17]};
    float* out = (float*)d_out;

    float *featT, *x0, *x1, *x2;
    cudaGetSymbolAddress((void**)&featT, g_featT);
    cudaGetSymbolAddress((void**)&x0, g_x0);
    cudaGetSymbolAddress((void**)&x1, g_x1);
    cudaGetSymbolAddress((void**)&x2, g_x2);

    const int HWs[4]     = {67200, 16800, 4200, 1050};
    const size_t offs[4] = {0, 17203200, 21504000, 22579200};
    for (int l = 0; l < 4; l++) {
        dim3 grid((HWs[l] + 31) / 32, 8), block(32, 8);
        transpose_kernel<<<grid, block>>>(feats[l], featT + offs[l], HWs[l]);
    }

    cudaFuncSetAttribute(roi_kernel, cudaFuncAttributeMaxDynamicSharedMemorySize, 50176);
    roi_kernel<<<NPROP, 256, 50176>>>(proposals);

    dim3 g6(1024 / 64, (NPROP + 127) / 128);  // (16, 8) = 128 blocks
    mma_gemm<true><<<g6, 256>>>(x0, fc6_w, fc6_b, x1, NPROP, 1024, 12544);
    mma_gemm<true><<<g6, 256>>>(x1, fc7_w, fc7_b, x2, NPROP, 1024, 1024);

    heads_kernel<<<NPROP, 128>>>(cls_w, cls_b, box_w, box_b,
                                 cos_w, cos_b, sin_w, sin_b,
                                 proposals, img, out);
}

// round 7
// speedup vs baseline: 3.2233x; 1.3139x over previous
#include <cuda_runtime.h>
#include <cuda_fp16.h>
#include <cstdint>

#define NPROP 1000
#define CCH 256
#define FEATLEN 12544   // 256*7*7
#define DH 1024

// ---- static scratch (no allocation allowed) ----
__device__ float  g_featT[22848000];            // transposed features [HW, C]
__device__ __half g_x0h[NPROP * FEATLEN];       // pooled ROI rows, fp16, k-permuted
__device__ __half g_w6T[DH * FEATLEN];          // fc6_w^T [1024][12544] fp16, k-permuted
__device__ __half g_x1h[NPROP * DH];            // fc6 out, fp16, k-permuted
__device__ __half g_w7T[DH * DH];               // fc7_w^T fp16, k-permuted
__device__ float  g_x2[NPROP * DH];             // fc7 out, fp32 plain

__constant__ int c_W[4]    = {336, 168, 84, 42};
__constant__ int c_H[4]    = {200, 100, 50, 25};
__constant__ int c_off[4]  = {0, 17203200, 21504000, 22579200};

// ======================= helpers ==========================================
__device__ __forceinline__ uint32_t smem_u32(const void* p) {
    return (uint32_t)__cvta_generic_to_shared(p);
}
__device__ __forceinline__ void cp_async16(uint32_t dst, const void* src, int srcsize) {
    asm volatile("cp.async.ca.shared.global [%0], [%1], 16, %2;\n"
                 :: "r"(dst), "l"(src), "r"(srcsize));
}
// k-pair permutation: within each group of 8 pairs (16 halves), store order
// [0,4,1,5,2,6,3,7]; logical pair q stored at 2*(q%4) + q/4.
__device__ __forceinline__ int kperm_pair(int q) { return ((q & 3) << 1) | (q >> 2); }
__device__ __forceinline__ int kperm_h(int k) {
    int q = (k >> 1) & 7;
    return (k & ~15) | (kperm_pair(q) << 1) | (k & 1);
}

// ======================= transpose [C,HW] -> [HW,C] (features) ============
__global__ void transpose_kernel(const float* __restrict__ in,
                                 float* __restrict__ out, int HW) {
    __shared__ float tile[32][33];
    int hw0 = blockIdx.x * 32;
    int c0  = blockIdx.y * 32;
    int x = hw0 + threadIdx.x;
#pragma unroll
    for (int i = 0; i < 32; i += 8) {
        int c = c0 + threadIdx.y + i;
        if (x < HW) tile[threadIdx.y + i][threadIdx.x] = in[(size_t)c * HW + x];
    }
    __syncthreads();
    int c = c0 + threadIdx.x;
#pragma unroll
    for (int i = 0; i < 32; i += 8) {
        int hw = hw0 + threadIdx.y + i;
        if (hw < HW) out[(size_t)hw * CCH + c] = tile[threadIdx.x][threadIdx.y + i];
    }
}

// ======================= weight transpose -> fp16 [N][K] permuted =========
// in [R, Cc] fp32 row-major -> out [Cc][R] fp16, R(=K)-index permuted
__global__ void transpose_w_h(const float* __restrict__ in, __half* __restrict__ out,
                              int R, int Cc) {
    __shared__ float tile[32][33];
    int c0 = blockIdx.x * 32, r0 = blockIdx.y * 32;
    int c = c0 + threadIdx.x;
#pragma unroll
    for (int i = 0; i < 32; i += 8) {
        int r = r0 + threadIdx.y + i;
        if (r < R) tile[threadIdx.y + i][threadIdx.x] = in[(size_t)r * Cc + c];
    }
    __syncthreads();
    int r = r0 + threadIdx.x;
#pragma unroll
    for (int i = 0; i < 32; i += 8) {
        int cc = c0 + threadIdx.y + i;
        if (r < R)
            out[(size_t)cc * R + kperm_h(r)] = __float2half(tile[threadIdx.x][threadIdx.y + i]);
    }
}

// ======================= ROI align + 2x2 avg pool =========================
__global__ void roi_kernel(const float* __restrict__ proposals) {
    extern __shared__ float stile[];  // 12544 floats
    __shared__ int   sx0[14], sx1[14], sy0[14], sy1[14];
    __shared__ float sfx[14], sfy[14];
    __shared__ int   svx[14], svy[14];
    __shared__ float sp[4];
    __shared__ int   s_li;

    int n = blockIdx.x;
    int tid = threadIdx.x;

    if (tid < 4) sp[tid] = proposals[n * 4 + tid];
    __syncthreads();
    float px1 = sp[0], py1 = sp[1], px2 = sp[2], py2 = sp[3];

    if (tid == 0) {
        float h = py2 - py1, w = px2 - px1;
        float sqrtarea = sqrtf(h * w);
        float lf = 4.0f + logf(sqrtarea / 224.0f + 1e-6f) / logf(2.0f);
        int lvl = (int)lf;
        lvl = min(max(lvl, 2), 5);
        s_li = lvl - 2;
    }
    __syncthreads();
    int li = s_li;
    int W = c_W[li], H = c_H[li];
    int Wp = W + 2, Hp = H + 2;
    float inv_stride = 1.0f / (float)(4 << li);
    float bx1 = px1 * inv_stride + 1.0f, by1 = py1 * inv_stride + 1.0f;
    float bx2 = px2 * inv_stride + 1.0f, by2 = py2 * inv_stride + 1.0f;

    if (tid < 14) {
        float g = ((float)tid + 0.5f) / 14.0f;
        float xc = bx1 + g * (bx2 - bx1) - 0.5f;
        svx[tid] = (xc >= -1.0f) && (xc <= (float)Wp);
        float cx = fminf(fmaxf(xc, 0.0f), (float)(Wp - 1));
        int lo = (int)floorf(cx);
        int hi = min(lo + 1, Wp - 1);
        sfx[tid] = cx - (float)lo;
        sx0[tid] = min(max(lo - 1, 0), W - 1);   // padded->orig (edge pad == clamp)
        sx1[tid] = min(max(hi - 1, 0), W - 1);
        float yc = by1 + g * (by2 - by1) - 0.5f;
        svy[tid] = (yc >= -1.0f) && (yc <= (float)Hp);
        float cy = fminf(fmaxf(yc, 0.0f), (float)(Hp - 1));
        int lo2 = (int)floorf(cy);
        int hi2 = min(lo2 + 1, Hp - 1);
        sfy[tid] = cy - (float)lo2;
        sy0[tid] = min(max(lo2 - 1, 0), H - 1);
        sy1[tid] = min(max(hi2 - 1, 0), H - 1);
    }
    __syncthreads();

    int c = tid;
    const float* fbase = g_featT + c_off[li];
#pragma unroll 1
    for (int oy = 0; oy < 7; oy++) {
#pragma unroll 1
        for (int ox = 0; ox < 7; ox++) {
            float acc = 0.0f;
#pragma unroll
            for (int s = 0; s < 4; s++) {
                int gy = 2 * oy + (s >> 1);
                int gx = 2 * ox + (s & 1);
                if (svx[gx] && svy[gy]) {
                    float fx = sfx[gx], fy = sfy[gy];
                    int x0i = sx0[gx], x1i = sx1[gx];
                    int y0i = sy0[gy], y1i = sy1[gy];
                    const float* r0 = fbase + (size_t)(y0i * W) * CCH;
                    const float* r1 = fbase + (size_t)(y1i * W) * CCH;
                    float v00 = r0[x0i * CCH + c];
                    float v01 = r0[x1i * CCH + c];
                    float v10 = r1[x0i * CCH + c];
                    float v11 = r1[x1i * CCH + c];
                    float v = v00 * ((1.0f - fy) * (1.0f - fx))
                            + v01 * ((1.0f - fy) * fx)
                            + v10 * (fy * (1.0f - fx))
                            + v11 * (fy * fx);
                    acc += v;
                }
            }
            stile[c * 49 + oy * 7 + ox] = acc * 0.25f;
        }
    }
    __syncthreads();
    __half* xrow = g_x0h + (size_t)n * FEATLEN;
    for (int i = tid; i < FEATLEN; i += 256)
        xrow[kperm_h(i)] = __float2half(stile[i]);
}

// ======================= fp16 mma.sync GEMM ===============================
// C = relu(A*Bt^T + bias). A [M,K] fp16 (k-permuted), Bt [N,K] fp16 (k-permuted).
// CTA 128x64, 8 warps (4m x 2n), warp tile 32x32 via m16n8k16.
// 4-stage cp.async. Fragments loaded as LDS.64 thanks to k-pair permutation.
#define NSTAGE   4
#define BKH      32                   // halves of K per stage (2 k16 steps)
#define ROW_B    80                   // smem row bytes: 64 data + 16 pad
#define A_TILE_B (128 * ROW_B)        // 10240
#define B_TILE_B (64 * ROW_B)         // 5120
#define STAGE_B  (A_TILE_B + B_TILE_B)

// MODE: 0 = write fp16 k-permuted (feeds next GEMM), 1 = write fp32 plain
template <int MODE>
__global__ __launch_bounds__(256) void hgemm(
        const __half* __restrict__ A, const __half* __restrict__ Bt,
        const float* __restrict__ bias, void* __restrict__ Cout,
        int M, int N, int K) {
    extern __shared__ char sm[];
    int tid = threadIdx.x, wid = tid >> 5, lane = tid & 31;
    int brow = blockIdx.y * 128, bcol = blockIdx.x * 64;
    int warp_m = (wid & 3) * 32, warp_n = (wid >> 2) * 32;
    int T = K / BKH;

    int t4 = lane & 3, g8 = lane >> 2;

    auto load_stage = [&](int t) {
        if (t < T) {
            char* sa = sm + (t % NSTAGE) * STAGE_B;
            int k0 = t * BKH;
            // A: 512 chunks of 16B (128 rows x 4)
#pragma unroll
            for (int i = 0; i < 2; i++) {
                int cid = tid + i * 256;
                int row = cid >> 2, q = cid & 3;
                int gr = brow + row;
                const __half* src = A + (size_t)min(gr, M - 1) * K + k0 + q * 8;
                cp_async16(smem_u32(sa + row * ROW_B + q * 16), src, gr < M ? 16 : 0);
            }
            // B: 256 chunks (64 rows x 4)
            {
                int row = tid >> 2, q = tid & 3;
                const __half* src = Bt + (size_t)(bcol + row) * K + k0 + q * 8;
                cp_async16(smem_u32(sa + A_TILE_B + row * ROW_B + q * 16), src, 16);
            }
        }
        asm volatile("cp.async.commit_group;\n" ::);
    };

    float acc[2][4][4];
#pragma unroll
    for (int i = 0; i < 2; i++)
#pragma unroll
        for (int j = 0; j < 4; j++)
#pragma unroll
            for (int r = 0; r < 4; r++) acc[i][j][r] = 0.0f;

    for (int t = 0; t < NSTAGE - 1; t++) load_stage(t);

    for (int t = 0; t < T; t++) {
        asm volatile("cp.async.wait_group %0;\n" :: "n"(NSTAGE - 2));
        __syncthreads();
        load_stage(t + NSTAGE - 1);

        const char* sa = sm + (t % NSTAGE) * STAGE_B;
#pragma unroll
        for (int ks = 0; ks < 2; ks++) {
            int off = ks * 32 + 8 * t4;
            uint2 alo[2], ahi[2], b[4];
#pragma unroll
            for (int i = 0; i < 2; i++) {
                const char* r0 = sa + (warp_m + i * 16 + g8) * ROW_B + off;
                alo[i] = *(const uint2*)r0;
                ahi[i] = *(const uint2*)(r0 + 8 * ROW_B);
            }
#pragma unroll
            for (int j = 0; j < 4; j++) {
                const char* rb = sa + A_TILE_B + (warp_n + j * 8 + g8) * ROW_B + off;
                b[j] = *(const uint2*)rb;
            }
#pragma unroll
            for (int i = 0; i < 2; i++)
#pragma unroll
                for (int j = 0; j < 4; j++) {
                    asm volatile(
                        "mma.sync.aligned.m16n8k16.row.col.f32.f16.f16.f32 "
                        "{%0,%1,%2,%3}, {%4,%5,%6,%7}, {%8,%9}, {%0,%1,%2,%3};\n"
                        : "+f"(acc[i][j][0]), "+f"(acc[i][j][1]),
                          "+f"(acc[i][j][2]), "+f"(acc[i][j][3])
                        : "r"(alo[i].x), "r"(ahi[i].x), "r"(alo[i].y), "r"(ahi[i].y),
                          "r"(b[j].x), "r"(b[j].y));
                }
        }
    }

    // ---- epilogue: bias + relu + store ----
#pragma unroll
    for (int i = 0; i < 2; i++) {
#pragma unroll
        for (int j = 0; j < 4; j++) {
            int col = bcol + warp_n + j * 8 + 2 * t4;
            float b0 = bias[col], b1 = bias[col + 1];
            int row0 = brow + warp_m + i * 16 + g8;
            float v0 = fmaxf(acc[i][j][0] + b0, 0.f);
            float v1 = fmaxf(acc[i][j][1] + b1, 0.f);
            float v2 = fmaxf(acc[i][j][2] + b0, 0.f);
            float v3 = fmaxf(acc[i][j][3] + b1, 0.f);
            if (MODE == 0) {
                // fp16, k-permuted (cols 2t,2t+1 form one k-pair; moves together)
                int sidx = (col & ~15) | (kperm_pair((col >> 1) & 7) << 1);
                __half* Ch = (__half*)Cout;
                if (row0 < M)
                    *(__half2*)(Ch + (size_t)row0 * N + sidx) = __floats2half2_rn(v0, v1);
                if (row0 + 8 < M)
                    *(__half2*)(Ch + (size_t)(row0 + 8) * N + sidx) = __floats2half2_rn(v2, v3);
            } else {
                float* Cf = (float*)Cout;
                if (row0 < M)
                    *(float2*)(Cf + (size_t)row0 * N + col) = make_float2(v0, v1);
                if (row0 + 8 < M)
                    *(float2*)(Cf + (size_t)(row0 + 8) * N + col) = make_float2(v2, v3);
            }
        }
    }
}

// ======================= heads + softmax + decode =========================
__global__ void heads_kernel(const float* __restrict__ cls_w, const float* __restrict__ cls_b,
                             const float* __restrict__ box_w, const float* __restrict__ box_b,
                             const float* __restrict__ cos_w, const float* __restrict__ cos_b,
                             const float* __restrict__ sin_w, const float* __restrict__ sin_b,
                             const float* __restrict__ proposals,
                             const float* __restrict__ img,
                             float* __restrict__ out) {
    int n = blockIdx.x, tid = threadIdx.x;
    __shared__ float xs[DH];
    __shared__ float hout[88];
    __shared__ float ev[81];
    __shared__ float red[2];

    for (int k = tid; k < DH; k += 128) xs[k] = g_x2[(size_t)n * DH + k];
    __syncthreads();

    if (tid < 81) {
        float a = 0.f;
        for (int k = 0; k < DH; k++) a = fmaf(xs[k], cls_w[k * 81 + tid], a);
        hout[tid] = a + cls_b[tid];
    } else if (tid < 85) {
        int j = tid - 81;
        float a = 0.f;
        for (int k = 0; k < DH; k++) a = fmaf(xs[k], box_w[k * 4 + j], a);
        hout[tid] = a + box_b[j];
    } else if (tid == 85) {
        float a = 0.f;
        for (int k = 0; k < DH; k++) a = fmaf(xs[k], cos_w[k], a);
        hout[85] = a + cos_b[0];
    } else if (tid == 86) {
        float a = 0.f;
        for (int k = 0; k < DH; k++) a = fmaf(xs[k], sin_w[k], a);
        hout[86] = a + sin_b[0];
    }
    __syncthreads();

    if (tid == 0) {
        float mx = hout[0];
        for (int j = 1; j < 81; j++) mx = fmaxf(mx, hout[j]);
        red[0] = mx;
    }
    __syncthreads();
    if (tid < 81) ev[tid] = expf(hout[tid] - red[0]);
    __syncthreads();
    if (tid == 0) {
        float s = 0.f;
        for (int j = 0; j < 81; j++) s += ev[j];
        red[1] = s;
    }
    __syncthreads();

    if (tid < 81) {
        out[n * 81 + tid]          = ev[tid] / red[1];
        out[81000 + n * 81 + tid]  = hout[tid];
    } else if (tid < 85) {
        out[162000 + n * 4 + (tid - 81)] = hout[tid];
    } else if (tid == 85) {
        out[166000 + n] = hout[85];
    } else if (tid == 86) {
        out[167000 + n] = hout[86];
    }

    if (tid == 0) {
        float x1p = proposals[n * 4 + 0], y1p = proposals[n * 4 + 1];
        float x2p = proposals[n * 4 + 2], y2p = proposals[n * 4 + 3];
        float tx = hout[81] / 10.0f, ty = hout[82] / 10.0f;
        float tw = hout[83] / 5.0f,  th = hout[84] / 5.0f;
        float wa = x2p - x1p, ha = y2p - y1p;
        float xa = (x1p + x2p) * 0.5f, ya = (y1p + y2p) * 0.5f;
        const float clipv = 4.430816798843313f;  // log(1344/16)
        float wb = expf(fminf(tw, clipv)) * wa;
        float hb = expf(fminf(th, clipv)) * ha;
        float xb = tx * wa + xa, yb = ty * ha + ya;
        float s0 = img[0], s1 = img[1];   // reference clips x by shape[0], y by shape[1]
        out[168000 + n * 4 + 0] = fminf(fmaxf(xb - wb * 0.5f, 0.f), s0);
        out[168000 + n * 4 + 1] = fminf(fmaxf(yb - hb * 0.5f, 0.f), s1);
        out[168000 + n * 4 + 2] = fminf(fmaxf(xb + wb * 0.5f, 0.f), s0);
        out[168000 + n * 4 + 3] = fminf(fmaxf(yb + hb * 0.5f, 0.f), s1);
    }
}

// ======================= launch =========================
extern "C" void kernel_launch(void* const* d_in, const int* in_sizes, int n_in,
                              void* d_out, int out_size) {
    const float* img       = (const float*)d_in[0];
    const float* proposals = (const float*)d_in[1];
    const float* fc6_w = (const float*)d_in[2];
    const float* fc6_b = (const float*)d_in[3];
    const float* fc7_w = (const float*)d_in[4];
    const float* fc7_b = (const float*)d_in[5];
    const float* cls_w = (const float*)d_in[6];
    const float* cls_b = (const float*)d_in[7];
    const float* box_w = (const float*)d_in[8];
    const float* box_b = (const float*)d_in[9];
    const float* cos_w = (const float*)d_in[10];
    const float* cos_b = (const float*)d_in[11];
    const float* sin_w = (const float*)d_in[12];
    const float* sin_b = (const float*)d_in[13];
    const float* feats[4] = {(const float*)d_in[14], (const float*)d_in[15],
                             (const float*)d_in[16], (const float*)d_in[17]};
    float* out = (float*)d_out;

    float *featT, *x2;
    __half *x0h, *x1h, *w6T, *w7T;
    cudaGetSymbolAddress((void**)&featT, g_featT);
    cudaGetSymbolAddress((void**)&x0h, g_x0h);
    cudaGetSymbolAddress((void**)&x1h, g_x1h);
    cudaGetSymbolAddress((void**)&x2, g_x2);
    cudaGetSymbolAddress((void**)&w6T, g_w6T);
    cudaGetSymbolAddress((void**)&w7T, g_w7T);

    const int HWs[4]     = {67200, 16800, 4200, 1050};
    const size_t offs[4] = {0, 17203200, 21504000, 22579200};
    for (int l = 0; l < 4; l++) {
        dim3 grid((HWs[l] + 31) / 32, 8), block(32, 8);
        transpose_kernel<<<grid, block>>>(feats[l], featT + offs[l], HWs[l]);
    }

    // weight transposes -> fp16 [N][K], k-permuted
    {
        dim3 b(32, 8);
        transpose_w_h<<<dim3(DH / 32, (FEATLEN + 31) / 32), b>>>(fc6_w, w6T, FEATLEN, DH);
        transpose_w_h<<<dim3(DH / 32, DH / 32),             b>>>(fc7_w, w7T, DH, DH);
    }

    cudaFuncSetAttribute(roi_kernel, cudaFuncAttributeMaxDynamicSharedMemorySize, 50176);
    roi_kernel<<<NPROP, 256, 50176>>>(proposals);

    const int smem_gemm = NSTAGE * STAGE_B;   // 61440
    cudaFuncSetAttribute(hgemm<0>, cudaFuncAttributeMaxDynamicSharedMemorySize, smem_gemm);
    cudaFuncSetAttribute(hgemm<1>, cudaFuncAttributeMaxDynamicSharedMemorySize, smem_gemm);
    dim3 g6(DH / 64, (NPROP + 127) / 128);    // (16, 8) = 128 CTAs
    hgemm<0><<<g6, 256, smem_gemm>>>(x0h, w6T, fc6_b, x1h, NPROP, DH, FEATLEN);
    hgemm<1><<<g6, 256, smem_gemm>>>(x1h, w7T, fc7_b, x2, NPROP, DH, DH);

    heads_kernel<<<NPROP, 128>>>(cls_w, cls_b, box_w, box_b,
                                 cos_w, cos_b, sin_w, sin_b,
                                 proposals, img, out);
}